// round 1
// baseline (speedup 1.0000x reference)
#include <cuda_runtime.h>
#include <math.h>

#define B   32
#define H   1024
#define TZ  16
#define TU  128
#define E   512
#define V   32000
#define XD  2560      // E + 2H
#define G3  3072      // 3H
#define LN_EPS 1e-3f

// ----------------- static scratch (allocation-free) -----------------
__device__ float d_hproj_z[B * H];
__device__ float d_hproj_u[B * H];
__device__ float d_gpart  [B * H];
__device__ float d_scores_z[B * TZ];
__device__ float d_scores_u[B * TU];
__device__ float d_zc      [B * TZ];
__device__ float d_ctx_z[B * H];
__device__ float d_ctx_u[B * H];
__device__ float d_x  [B * XD];
__device__ float d_gi [B * G3];
__device__ float d_gh [B * G3];
__device__ float d_gru[B * H];
__device__ float d_gen[B * V];
__device__ float d_rmax[B];
__device__ float d_rsum[B];
__device__ float d_cp[B * TZ];

// ----------------- skinny proj: out[b][j] += sum_k in[b][k]*W[k*ldw+j] (+bias on y==0) ----
// grid(N/256, KSPLIT), 256 thr. K chunk must be multiple of 64.
__global__ void skinny_proj(const float* __restrict__ in, int K,
                            const float* __restrict__ W, int ldw,
                            const float* __restrict__ bias,
                            float* __restrict__ out, int N, int kchunk)
{
    int j  = blockIdx.x * 256 + threadIdx.x;
    int k0 = blockIdx.y * kchunk;
    int k1 = k0 + kchunk;
    float acc[B];
#pragma unroll
    for (int b = 0; b < B; b++) acc[b] = 0.f;
    __shared__ float xs[B][64];
    for (int kb = k0; kb < k1; kb += 64) {
        for (int e = threadIdx.x; e < B * 64; e += 256) {
            int bb = e >> 6, kk = e & 63;
            xs[bb][kk] = in[bb * K + kb + kk];
        }
        __syncthreads();
#pragma unroll 4
        for (int kk = 0; kk < 64; kk++) {
            float w = W[(kb + kk) * ldw + j];
#pragma unroll
            for (int b = 0; b < B; b++) acc[b] = fmaf(xs[b][kk], w, acc[b]);
        }
        __syncthreads();
    }
    float bv = (blockIdx.y == 0) ? bias[j] : 0.f;
    for (int b = 0; b < B; b++) atomicAdd(&out[b * N + j], acc[b] + bv);
}

// ----------------- fused energy GEMM + tanh + dot(v) -> scores -----------------
// A: [M][H] rows r=t*B+b. Wp: rows k -> Wp[k*H + n] (pointer pre-offset).
// scores[b*T+t] += sum_n tanh(A@Wp + addv[b][n]) * v[n]   (atomic over N-tiles)
#define BM 64
#define BN 64
#define BK 16
__global__ void energy_score(const float* __restrict__ A,
                             const float* __restrict__ Wp,
                             const float* __restrict__ addv,
                             const float* __restrict__ vvec,
                             float* __restrict__ out,
                             int M, int T)
{
    __shared__ float As[BK][BM];
    __shared__ float Bs[BK][BN];
    int row0 = blockIdx.y * BM, col0 = blockIdx.x * BN;
    int tx = threadIdx.x & 15, ty = threadIdx.x >> 4;
    float acc[4][4] = {};
    for (int k0 = 0; k0 < H; k0 += BK) {
        for (int e = threadIdx.x; e < BM * BK; e += 256) {
            int m = e / BK, kk = e % BK;
            As[kk][m] = A[(row0 + m) * H + k0 + kk];
        }
        for (int e = threadIdx.x; e < BN * BK; e += 256) {
            int kk = e / BN, n = e % BN;
            Bs[kk][n] = Wp[(k0 + kk) * H + col0 + n];
        }
        __syncthreads();
#pragma unroll
        for (int kk = 0; kk < BK; kk++) {
            float a[4], bb[4];
#pragma unroll
            for (int i = 0; i < 4; i++) a[i] = As[kk][ty * 4 + i];
#pragma unroll
            for (int j = 0; j < 4; j++) bb[j] = Bs[kk][tx * 4 + j];
#pragma unroll
            for (int i = 0; i < 4; i++)
#pragma unroll
                for (int j = 0; j < 4; j++) acc[i][j] = fmaf(a[i], bb[j], acc[i][j]);
        }
        __syncthreads();
    }
    __shared__ float red[BM][16];
#pragma unroll
    for (int i = 0; i < 4; i++) {
        int r = row0 + ty * 4 + i;
        int bidx = r % B;
        float s = 0.f;
#pragma unroll
        for (int j = 0; j < 4; j++) {
            int n = col0 + tx * 4 + j;
            float ev = tanhf(acc[i][j] + addv[bidx * H + n]);
            s = fmaf(ev, vvec[n], s);
        }
        red[ty * 4 + i][tx] = s;
    }
    __syncthreads();
    for (int lr = threadIdx.x; lr < BM; lr += 256) {
        float t = 0.f;
#pragma unroll
        for (int c = 0; c < 16; c++) t += red[lr][c];
        int r = row0 + lr;
        atomicAdd(&out[(r % B) * T + (r / B)], t);
    }
}

// ----------------- softmax over scores + weighted context -----------------
__global__ void attn_ctx(const float* __restrict__ scores,
                         const float* __restrict__ enc,
                         float* __restrict__ ctx, int T)
{
    int b = blockIdx.x, tid = threadIdx.x;
    __shared__ float w[TU];
    __shared__ float inv_s;
    if (tid < T) w[tid] = scores[b * T + tid];
    __syncthreads();
    if (tid == 0) {
        float mx = -1e30f;
        for (int t = 0; t < T; t++) mx = fmaxf(mx, w[t]);
        float s = 0.f;
        for (int t = 0; t < T; t++) { float e = expf(w[t] - mx); w[t] = e; s += e; }
        inv_s = 1.f / s;
    }
    __syncthreads();
    int j = blockIdx.y * 256 + tid;
    float acc = 0.f;
    for (int t = 0; t < T; t++) acc = fmaf(w[t], enc[(t * B + b) * H + j], acc);
    ctx[b * H + j] = acc * inv_s;
}

// ----------------- build x = [ctx_z | ctx_u | emb[m_t]] -----------------
__global__ void build_x(const float* __restrict__ cz, const float* __restrict__ cu,
                        const float* __restrict__ emb, const int* __restrict__ mt,
                        float* __restrict__ x)
{
    int idx = blockIdx.x * 256 + threadIdx.x;
    if (idx >= B * XD) return;
    int b = idx / XD, k = idx % XD;
    float vl;
    if (k < H)            vl = cz[b * H + k];
    else if (k < 2 * H)   vl = cu[b * H + (k - H)];
    else                  vl = emb[(long)mt[b] * E + (k - 2 * H)];
    x[idx] = vl;
}

// ----------------- row-dot GEMM: out[b][j] = sum_k in[b][k]*W[j*K+k] + bias[j] ----
// tile: 16 j per block, all 32 b. grid(N/16), 256 thr, 2 outputs/thread.
__global__ void rowdot(const float* __restrict__ in, int K,
                       const float* __restrict__ W,
                       const float* __restrict__ bias,
                       float* __restrict__ out, int N)
{
    int j0 = blockIdx.x * 16;
    __shared__ float Ws[16][65];
    __shared__ float Xs[B][64];
    int tid = threadIdx.x;
    int b1 = tid >> 4,        j1 = tid & 15;
    int b2 = (tid + 256) >> 4, j2 = tid & 15;
    float a1 = 0.f, a2 = 0.f;
    for (int k0 = 0; k0 < K; k0 += 64) {
        for (int e = tid; e < 16 * 64; e += 256) {
            int jl = e >> 6, kk = e & 63;
            Ws[jl][kk] = W[(j0 + jl) * K + k0 + kk];
        }
        for (int e = tid; e < B * 64; e += 256) {
            int bb = e >> 6, kk = e & 63;
            Xs[bb][kk] = in[bb * K + k0 + kk];
        }
        __syncthreads();
#pragma unroll 8
        for (int kk = 0; kk < 64; kk++) {
            a1 = fmaf(Xs[b1][kk], Ws[j1][kk], a1);
            a2 = fmaf(Xs[b2][kk], Ws[j2][kk], a2);
        }
        __syncthreads();
    }
    out[b1 * N + j0 + j1] = a1 + bias[j0 + j1];
    out[b2 * N + j0 + j2] = a2 + bias[j0 + j2];
}

// ----------------- GRU gates + layernorm (ddof=1, (sigma+eps) denom) -----------------
__global__ void gru_ln(const float* __restrict__ gi, const float* __restrict__ gh,
                       const float* __restrict__ h,
                       const float* __restrict__ lna, const float* __restrict__ lnb,
                       float* __restrict__ hnew_out, float* __restrict__ gru_out)
{
    int b = blockIdx.x, j = threadIdx.x;   // 1024 threads
    float ir = gi[b * G3 + j], iz = gi[b * G3 + H + j], inn = gi[b * G3 + 2 * H + j];
    float hr = gh[b * G3 + j], hz = gh[b * G3 + H + j], hn  = gh[b * G3 + 2 * H + j];
    float r  = 1.f / (1.f + expf(-(ir + hr)));
    float zg = 1.f / (1.f + expf(-(iz + hz)));
    float n  = tanhf(inn + r * hn);
    float hv = h[b * H + j];
    float hnew = (1.f - zg) * n + zg * hv;
    hnew_out[b * H + j] = hnew;
    __shared__ float sh[1024];
    sh[j] = hnew; __syncthreads();
    for (int s = 512; s > 0; s >>= 1) { if (j < s) sh[j] += sh[j + s]; __syncthreads(); }
    float mu = sh[0] * (1.f / H); __syncthreads();
    float d = hnew - mu;
    sh[j] = d * d; __syncthreads();
    for (int s = 512; s > 0; s >>= 1) { if (j < s) sh[j] += sh[j + s]; __syncthreads(); }
    float sigma = sqrtf(sh[0] / (float)(H - 1));
    gru_out[b * H + j] = d / (sigma + LN_EPS) * lna[j] + lnb[j];
}

// ----------------- vocab projection: gen[b][v] += sum_k g[b][k]*W_proj[k*V+v] ------
// grid(V/256, 4 ksplit), 256 thr.
__global__ void gen_gemm(const float* __restrict__ g, const float* __restrict__ Wp,
                         float* __restrict__ gen)
{
    int v = blockIdx.x * 256 + threadIdx.x;
    int kbase = blockIdx.y * 256;
    __shared__ float gs[B][256];
    for (int e = threadIdx.x; e < B * 256; e += 256) {
        int bb = e >> 8, kk = e & 255;
        gs[bb][kk] = g[bb * H + kbase + kk];
    }
    __syncthreads();
    float acc[B] = {};
#pragma unroll 4
    for (int kk = 0; kk < 256; kk++) {
        float w = Wp[(long)(kbase + kk) * V + v];
#pragma unroll
        for (int b = 0; b < B; b++) acc[b] = fmaf(gs[b][kk], w, acc[b]);
    }
#pragma unroll
    for (int b = 0; b < B; b++) atomicAdd(&gen[b * V + v], acc[b]);
}

// ----------------- softmax stats over [gen | zc] per b -----------------
__global__ void softmax_stats(const float* __restrict__ gen, const float* __restrict__ bproj,
                              const float* __restrict__ zc,  const float* __restrict__ bv1,
                              float* __restrict__ rmax, float* __restrict__ rsum,
                              float* __restrict__ cp)
{
    int b = blockIdx.x, tid = threadIdx.x;  // 256 thr
    float bz = bv1[0];
    float mx = -1e30f;
    for (int v = tid; v < V; v += 256) mx = fmaxf(mx, gen[b * V + v] + bproj[v]);
    if (tid < TZ) mx = fmaxf(mx, zc[b * TZ + tid] + bz);
    __shared__ float sh[256];
    sh[tid] = mx; __syncthreads();
    for (int s = 128; s > 0; s >>= 1) { if (tid < s) sh[tid] = fmaxf(sh[tid], sh[tid + s]); __syncthreads(); }
    mx = sh[0]; __syncthreads();
    float s = 0.f;
    for (int v = tid; v < V; v += 256) s += __expf(gen[b * V + v] + bproj[v] - mx);
    if (tid < TZ) s += __expf(zc[b * TZ + tid] + bz - mx);
    sh[tid] = s; __syncthreads();
    for (int st = 128; st > 0; st >>= 1) { if (tid < st) sh[tid] += sh[tid + st]; __syncthreads(); }
    s = sh[0];
    if (tid == 0) { rmax[b] = mx; rsum[b] = s; }
    if (tid < TZ) cp[b * TZ + tid] = __expf(zc[b * TZ + tid] + bz - mx) / s;
}

// ----------------- final: proba = gen_p + mask*(copy_p @ pz) -----------------
__global__ void final_combine(const float* __restrict__ gen, const float* __restrict__ bproj,
                              const float* __restrict__ pz,
                              const float* __restrict__ rmax, const float* __restrict__ rsum,
                              const float* __restrict__ cp,
                              float* __restrict__ out)
{
    int b = blockIdx.y;
    int v = blockIdx.x * 256 + threadIdx.x;
    __shared__ float cps[TZ];
    __shared__ float st[2];
    if (threadIdx.x < TZ) cps[threadIdx.x] = cp[b * TZ + threadIdx.x];
    if (threadIdx.x == 0) { st[0] = rmax[b]; st[1] = 1.f / rsum[b]; }
    __syncthreads();
    float gp = __expf(gen[b * V + v] + bproj[v] - st[0]) * st[1];
    float acc = 0.f;
#pragma unroll
    for (int t = 0; t < TZ; t++) acc = fmaf(cps[t], pz[(long)(t * B + b) * V + v], acc);
    out[b * V + v] = gp + (v >= 4 ? acc : 0.f);
}

// ===================================================================
extern "C" void kernel_launch(void* const* d_in, const int* in_sizes, int n_in,
                              void* d_out, int out_size)
{
    const float* z_enc  = (const float*)d_in[0];
    const float* pz     = (const float*)d_in[1];
    const float* u_enc  = (const float*)d_in[2];
    const int*   mt     = (const int*)  d_in[3];
    const float* h      = (const float*)d_in[4];
    const float* emb    = (const float*)d_in[5];
    const float* Wa_z   = (const float*)d_in[6];
    const float* ba_z   = (const float*)d_in[7];
    const float* v_z    = (const float*)d_in[8];
    const float* Wa_u   = (const float*)d_in[9];
    const float* ba_u   = (const float*)d_in[10];
    const float* v_u    = (const float*)d_in[11];
    const float* W_ih   = (const float*)d_in[12];
    const float* W_hh   = (const float*)d_in[13];
    const float* b_ih   = (const float*)d_in[14];
    const float* b_hh   = (const float*)d_in[15];
    const float* ln_a   = (const float*)d_in[16];
    const float* ln_b   = (const float*)d_in[17];
    const float* W_proj = (const float*)d_in[18];
    const float* b_proj = (const float*)d_in[19];
    const float* W_c    = (const float*)d_in[20];
    const float* b_c    = (const float*)d_in[21];
    const float* W_v1   = (const float*)d_in[22];
    const float* b_v1   = (const float*)d_in[23];
    float* out = (float*)d_out;

    float *hpz, *hpu, *gpart, *sz, *su, *zcb, *cz, *cu, *xb, *gib, *ghb, *grub, *genb, *rmx, *rsm, *cpb;
    cudaGetSymbolAddress((void**)&hpz,  d_hproj_z);
    cudaGetSymbolAddress((void**)&hpu,  d_hproj_u);
    cudaGetSymbolAddress((void**)&gpart,d_gpart);
    cudaGetSymbolAddress((void**)&sz,   d_scores_z);
    cudaGetSymbolAddress((void**)&su,   d_scores_u);
    cudaGetSymbolAddress((void**)&zcb,  d_zc);
    cudaGetSymbolAddress((void**)&cz,   d_ctx_z);
    cudaGetSymbolAddress((void**)&cu,   d_ctx_u);
    cudaGetSymbolAddress((void**)&xb,   d_x);
    cudaGetSymbolAddress((void**)&gib,  d_gi);
    cudaGetSymbolAddress((void**)&ghb,  d_gh);
    cudaGetSymbolAddress((void**)&grub, d_gru);
    cudaGetSymbolAddress((void**)&genb, d_gen);
    cudaGetSymbolAddress((void**)&rmx,  d_rmax);
    cudaGetSymbolAddress((void**)&rsm,  d_rsum);
    cudaGetSymbolAddress((void**)&cpb,  d_cp);

    // zero atomic accumulators
    cudaMemsetAsync(hpz,  0, B * H  * sizeof(float));
    cudaMemsetAsync(hpu,  0, B * H  * sizeof(float));
    cudaMemsetAsync(gpart,0, B * H  * sizeof(float));
    cudaMemsetAsync(sz,   0, B * TZ * sizeof(float));
    cudaMemsetAsync(su,   0, B * TU * sizeof(float));
    cudaMemsetAsync(zcb,  0, B * TZ * sizeof(float));
    cudaMemsetAsync(genb, 0, B * V  * sizeof(float));

    // hidden-part of attention energies:  h @ Wa[:H] + ba
    skinny_proj<<<dim3(4, 4), 256>>>(h, H, Wa_z, H, ba_z, hpz, H, 256);
    skinny_proj<<<dim3(4, 4), 256>>>(h, H, Wa_u, H, ba_u, hpu, H, 256);

    // enc-part + tanh + dot(v) -> scores
    energy_score<<<dim3(16, (TZ * B) / BM), 256>>>(z_enc, Wa_z + H * H, hpz, v_z, sz, TZ * B, TZ);
    energy_score<<<dim3(16, (TU * B) / BM), 256>>>(u_enc, Wa_u + H * H, hpu, v_u, su, TU * B, TU);

    // softmax + context
    attn_ctx<<<dim3(B, 4), 256>>>(sz, z_enc, cz, TZ);
    attn_ctx<<<dim3(B, 4), 256>>>(su, u_enc, cu, TU);

    // x = [ctx_z | ctx_u | emb gather]
    build_x<<<(B * XD + 255) / 256, 256>>>(cz, cu, emb, mt, xb);

    // GRU gates
    rowdot<<<G3 / 16, 256>>>(xb, XD, W_ih, b_ih, gib, G3);
    rowdot<<<G3 / 16, 256>>>(h,  H,  W_hh, b_hh, ghb, G3);

    // gates + layernorm; writes h_new into the tail of d_out
    gru_ln<<<B, 1024>>>(gib, ghb, h, ln_a, ln_b, out + (long)B * V, grub);

    // copy branch: gru-part of W_c, then fused z_enc@W_c[:H] + tanh + dot(W_v1)
    skinny_proj<<<dim3(4, 4), 256>>>(grub, H, W_c + H * H, H, b_c, gpart, H, 256);
    energy_score<<<dim3(16, (TZ * B) / BM), 256>>>(z_enc, W_c, gpart, W_v1, zcb, TZ * B, TZ);

    // vocab projection
    gen_gemm<<<dim3(V / 256, 4), 256>>>(grub, W_proj, genb);

    // joint softmax over [gen | zc], then combine with copy distribution
    softmax_stats<<<B, 256>>>(genb, b_proj, zcb, b_v1, rmx, rsm, cpb);
    final_combine<<<dim3(V / 256, B), 256>>>(genb, b_proj, pz, rmx, rsm, cpb, out);

    (void)in_sizes; (void)n_in; (void)out_size;
}

// round 2
// speedup vs baseline: 1.0001x; 1.0001x over previous
#include <cuda_runtime.h>
#include <math.h>

#define B   32
#define H   1024
#define TZ  16
#define TU  128
#define E   512
#define V   32000
#define XD  2560      // E + 2H
#define G3  3072      // 3H
#define LN_EPS 1e-3f

// ----------------- static scratch (allocation-free) -----------------
__device__ float d_hproj_z[B * H];
__device__ float d_hproj_u[B * H];
__device__ float d_gpart  [B * H];
__device__ float d_scores_z[B * TZ];
__device__ float d_scores_u[B * TU];
__device__ float d_zc      [B * TZ];
__device__ float d_ctx_z[B * H];
__device__ float d_ctx_u[B * H];
__device__ float d_x  [B * XD];
__device__ float d_gi [B * G3];
__device__ float d_gh [B * G3];
__device__ float d_gru[B * H];
__device__ float d_gen[B * V];
__device__ float d_rmax[B];
__device__ float d_rsum[B];
__device__ float d_cp[B * TZ];

// ----------------- skinny proj: out[b][j] += sum_k in[b][k]*W[k*ldw+j] (+bias on y==0) ----
// grid(N/256, KSPLIT), 256 thr. K chunk must be multiple of 64.
__global__ void skinny_proj(const float* __restrict__ in, int K,
                            const float* __restrict__ W, int ldw,
                            const float* __restrict__ bias,
                            float* __restrict__ out, int N, int kchunk)
{
    int j  = blockIdx.x * 256 + threadIdx.x;
    int k0 = blockIdx.y * kchunk;
    int k1 = k0 + kchunk;
    float acc[B];
#pragma unroll
    for (int b = 0; b < B; b++) acc[b] = 0.f;
    __shared__ float xs[B][64];
    for (int kb = k0; kb < k1; kb += 64) {
        for (int e = threadIdx.x; e < B * 64; e += 256) {
            int bb = e >> 6, kk = e & 63;
            xs[bb][kk] = in[bb * K + kb + kk];
        }
        __syncthreads();
#pragma unroll 4
        for (int kk = 0; kk < 64; kk++) {
            float w = W[(kb + kk) * ldw + j];
#pragma unroll
            for (int b = 0; b < B; b++) acc[b] = fmaf(xs[b][kk], w, acc[b]);
        }
        __syncthreads();
    }
    float bv = (blockIdx.y == 0) ? bias[j] : 0.f;
    for (int b = 0; b < B; b++) atomicAdd(&out[b * N + j], acc[b] + bv);
}

// ----------------- fused energy GEMM + tanh + dot(v) -> scores -----------------
// A: [M][H] rows r=t*B+b. Wp: rows k -> Wp[k*H + n] (pointer pre-offset).
// scores[b*T+t] += sum_n tanh(A@Wp + addv[b][n]) * v[n]   (atomic over N-tiles)
#define BM 64
#define BN 64
#define BK 16
__global__ void energy_score(const float* __restrict__ A,
                             const float* __restrict__ Wp,
                             const float* __restrict__ addv,
                             const float* __restrict__ vvec,
                             float* __restrict__ out,
                             int M, int T)
{
    __shared__ float As[BK][BM];
    __shared__ float Bs[BK][BN];
    int row0 = blockIdx.y * BM, col0 = blockIdx.x * BN;
    int tx = threadIdx.x & 15, ty = threadIdx.x >> 4;
    float acc[4][4] = {};
    for (int k0 = 0; k0 < H; k0 += BK) {
        for (int e = threadIdx.x; e < BM * BK; e += 256) {
            int m = e / BK, kk = e % BK;
            As[kk][m] = A[(row0 + m) * H + k0 + kk];
        }
        for (int e = threadIdx.x; e < BN * BK; e += 256) {
            int kk = e / BN, n = e % BN;
            Bs[kk][n] = Wp[(k0 + kk) * H + col0 + n];
        }
        __syncthreads();
#pragma unroll
        for (int kk = 0; kk < BK; kk++) {
            float a[4], bb[4];
#pragma unroll
            for (int i = 0; i < 4; i++) a[i] = As[kk][ty * 4 + i];
#pragma unroll
            for (int j = 0; j < 4; j++) bb[j] = Bs[kk][tx * 4 + j];
#pragma unroll
            for (int i = 0; i < 4; i++)
#pragma unroll
                for (int j = 0; j < 4; j++) acc[i][j] = fmaf(a[i], bb[j], acc[i][j]);
        }
        __syncthreads();
    }
    __shared__ float red[BM][16];
#pragma unroll
    for (int i = 0; i < 4; i++) {
        int r = row0 + ty * 4 + i;
        int bidx = r % B;
        float s = 0.f;
#pragma unroll
        for (int j = 0; j < 4; j++) {
            int n = col0 + tx * 4 + j;
            float ev = tanhf(acc[i][j] + addv[bidx * H + n]);
            s = fmaf(ev, vvec[n], s);
        }
        red[ty * 4 + i][tx] = s;
    }
    __syncthreads();
    for (int lr = threadIdx.x; lr < BM; lr += 256) {
        float t = 0.f;
#pragma unroll
        for (int c = 0; c < 16; c++) t += red[lr][c];
        int r = row0 + lr;
        atomicAdd(&out[(r % B) * T + (r / B)], t);
    }
}

// ----------------- softmax over scores + weighted context -----------------
__global__ void attn_ctx(const float* __restrict__ scores,
                         const float* __restrict__ enc,
                         float* __restrict__ ctx, int T)
{
    int b = blockIdx.x, tid = threadIdx.x;
    __shared__ float w[TU];
    __shared__ float inv_s;
    if (tid < T) w[tid] = scores[b * T + tid];
    __syncthreads();
    if (tid == 0) {
        float mx = -1e30f;
        for (int t = 0; t < T; t++) mx = fmaxf(mx, w[t]);
        float s = 0.f;
        for (int t = 0; t < T; t++) { float e = expf(w[t] - mx); w[t] = e; s += e; }
        inv_s = 1.f / s;
    }
    __syncthreads();
    int j = blockIdx.y * 256 + tid;
    float acc = 0.f;
    for (int t = 0; t < T; t++) acc = fmaf(w[t], enc[(t * B + b) * H + j], acc);
    ctx[b * H + j] = acc * inv_s;
}

// ----------------- build x = [ctx_z | ctx_u | emb[m_t]] -----------------
__global__ void build_x(const float* __restrict__ cz, const float* __restrict__ cu,
                        const float* __restrict__ emb, const int* __restrict__ mt,
                        float* __restrict__ x)
{
    int idx = blockIdx.x * 256 + threadIdx.x;
    if (idx >= B * XD) return;
    int b = idx / XD, k = idx % XD;
    float vl;
    if (k < H)            vl = cz[b * H + k];
    else if (k < 2 * H)   vl = cu[b * H + (k - H)];
    else                  vl = emb[(long)mt[b] * E + (k - 2 * H)];
    x[idx] = vl;
}

// ----------------- row-dot GEMM: out[b][j] = sum_k in[b][k]*W[j*K+k] + bias[j] ----
// tile: 16 j per block, all 32 b. grid(N/16), 256 thr, 2 outputs/thread.
__global__ void rowdot(const float* __restrict__ in, int K,
                       const float* __restrict__ W,
                       const float* __restrict__ bias,
                       float* __restrict__ out, int N)
{
    int j0 = blockIdx.x * 16;
    __shared__ float Ws[16][65];
    __shared__ float Xs[B][64];
    int tid = threadIdx.x;
    int b1 = tid >> 4,        j1 = tid & 15;
    int b2 = (tid + 256) >> 4, j2 = tid & 15;
    float a1 = 0.f, a2 = 0.f;
    for (int k0 = 0; k0 < K; k0 += 64) {
        for (int e = tid; e < 16 * 64; e += 256) {
            int jl = e >> 6, kk = e & 63;
            Ws[jl][kk] = W[(j0 + jl) * K + k0 + kk];
        }
        for (int e = tid; e < B * 64; e += 256) {
            int bb = e >> 6, kk = e & 63;
            Xs[bb][kk] = in[bb * K + k0 + kk];
        }
        __syncthreads();
#pragma unroll 8
        for (int kk = 0; kk < 64; kk++) {
            a1 = fmaf(Xs[b1][kk], Ws[j1][kk], a1);
            a2 = fmaf(Xs[b2][kk], Ws[j2][kk], a2);
        }
        __syncthreads();
    }
    out[b1 * N + j0 + j1] = a1 + bias[j0 + j1];
    out[b2 * N + j0 + j2] = a2 + bias[j0 + j2];
}

// ----------------- GRU gates + layernorm (ddof=1, (sigma+eps) denom) -----------------
__global__ void gru_ln(const float* __restrict__ gi, const float* __restrict__ gh,
                       const float* __restrict__ h,
                       const float* __restrict__ lna, const float* __restrict__ lnb,
                       float* __restrict__ hnew_out, float* __restrict__ gru_out)
{
    int b = blockIdx.x, j = threadIdx.x;   // 1024 threads
    float ir = gi[b * G3 + j], iz = gi[b * G3 + H + j], inn = gi[b * G3 + 2 * H + j];
    float hr = gh[b * G3 + j], hz = gh[b * G3 + H + j], hn  = gh[b * G3 + 2 * H + j];
    float r  = 1.f / (1.f + expf(-(ir + hr)));
    float zg = 1.f / (1.f + expf(-(iz + hz)));
    float n  = tanhf(inn + r * hn);
    float hv = h[b * H + j];
    float hnew = (1.f - zg) * n + zg * hv;
    hnew_out[b * H + j] = hnew;
    __shared__ float sh[1024];
    sh[j] = hnew; __syncthreads();
    for (int s = 512; s > 0; s >>= 1) { if (j < s) sh[j] += sh[j + s]; __syncthreads(); }
    float mu = sh[0] * (1.f / H); __syncthreads();
    float d = hnew - mu;
    sh[j] = d * d; __syncthreads();
    for (int s = 512; s > 0; s >>= 1) { if (j < s) sh[j] += sh[j + s]; __syncthreads(); }
    float sigma = sqrtf(sh[0] / (float)(H - 1));
    gru_out[b * H + j] = d / (sigma + LN_EPS) * lna[j] + lnb[j];
}

// ----------------- vocab projection: gen[b][v] += sum_k g[b][k]*W_proj[k*V+v] ------
// grid(V/256, 4 ksplit), 256 thr.
__global__ void gen_gemm(const float* __restrict__ g, const float* __restrict__ Wp,
                         float* __restrict__ gen)
{
    int v = blockIdx.x * 256 + threadIdx.x;
    int kbase = blockIdx.y * 256;
    __shared__ float gs[B][256];
    for (int e = threadIdx.x; e < B * 256; e += 256) {
        int bb = e >> 8, kk = e & 255;
        gs[bb][kk] = g[bb * H + kbase + kk];
    }
    __syncthreads();
    float acc[B] = {};
#pragma unroll 4
    for (int kk = 0; kk < 256; kk++) {
        float w = Wp[(long)(kbase + kk) * V + v];
#pragma unroll
        for (int b = 0; b < B; b++) acc[b] = fmaf(gs[b][kk], w, acc[b]);
    }
#pragma unroll
    for (int b = 0; b < B; b++) atomicAdd(&gen[b * V + v], acc[b]);
}

// ----------------- softmax stats over [gen | zc] per b -----------------
__global__ void softmax_stats(const float* __restrict__ gen, const float* __restrict__ bproj,
                              const float* __restrict__ zc,  const float* __restrict__ bv1,
                              float* __restrict__ rmax, float* __restrict__ rsum,
                              float* __restrict__ cp)
{
    int b = blockIdx.x, tid = threadIdx.x;  // 256 thr
    float bz = bv1[0];
    float mx = -1e30f;
    for (int v = tid; v < V; v += 256) mx = fmaxf(mx, gen[b * V + v] + bproj[v]);
    if (tid < TZ) mx = fmaxf(mx, zc[b * TZ + tid] + bz);
    __shared__ float sh[256];
    sh[tid] = mx; __syncthreads();
    for (int s = 128; s > 0; s >>= 1) { if (tid < s) sh[tid] = fmaxf(sh[tid], sh[tid + s]); __syncthreads(); }
    mx = sh[0]; __syncthreads();
    float s = 0.f;
    for (int v = tid; v < V; v += 256) s += __expf(gen[b * V + v] + bproj[v] - mx);
    if (tid < TZ) s += __expf(zc[b * TZ + tid] + bz - mx);
    sh[tid] = s; __syncthreads();
    for (int st = 128; st > 0; st >>= 1) { if (tid < st) sh[tid] += sh[tid + st]; __syncthreads(); }
    s = sh[0];
    if (tid == 0) { rmax[b] = mx; rsum[b] = s; }
    if (tid < TZ) cp[b * TZ + tid] = __expf(zc[b * TZ + tid] + bz - mx) / s;
}

// ----------------- final: proba = gen_p + mask*(copy_p @ pz) -----------------
__global__ void final_combine(const float* __restrict__ gen, const float* __restrict__ bproj,
                              const float* __restrict__ pz,
                              const float* __restrict__ rmax, const float* __restrict__ rsum,
                              const float* __restrict__ cp,
                              float* __restrict__ out)
{
    int b = blockIdx.y;
    int v = blockIdx.x * 256 + threadIdx.x;
    __shared__ float cps[TZ];
    __shared__ float st[2];
    if (threadIdx.x < TZ) cps[threadIdx.x] = cp[b * TZ + threadIdx.x];
    if (threadIdx.x == 0) { st[0] = rmax[b]; st[1] = 1.f / rsum[b]; }
    __syncthreads();
    float gp = __expf(gen[b * V + v] + bproj[v] - st[0]) * st[1];
    float acc = 0.f;
#pragma unroll
    for (int t = 0; t < TZ; t++) acc = fmaf(cps[t], pz[(long)(t * B + b) * V + v], acc);
    out[b * V + v] = gp + (v >= 4 ? acc : 0.f);
}

// ===================================================================
extern "C" void kernel_launch(void* const* d_in, const int* in_sizes, int n_in,
                              void* d_out, int out_size)
{
    const float* z_enc  = (const float*)d_in[0];
    const float* pz     = (const float*)d_in[1];
    const float* u_enc  = (const float*)d_in[2];
    const int*   mt     = (const int*)  d_in[3];
    const float* h      = (const float*)d_in[4];
    const float* emb    = (const float*)d_in[5];
    const float* Wa_z   = (const float*)d_in[6];
    const float* ba_z   = (const float*)d_in[7];
    const float* v_z    = (const float*)d_in[8];
    const float* Wa_u   = (const float*)d_in[9];
    const float* ba_u   = (const float*)d_in[10];
    const float* v_u    = (const float*)d_in[11];
    const float* W_ih   = (const float*)d_in[12];
    const float* W_hh   = (const float*)d_in[13];
    const float* b_ih   = (const float*)d_in[14];
    const float* b_hh   = (const float*)d_in[15];
    const float* ln_a   = (const float*)d_in[16];
    const float* ln_b   = (const float*)d_in[17];
    const float* W_proj = (const float*)d_in[18];
    const float* b_proj = (const float*)d_in[19];
    const float* W_c    = (const float*)d_in[20];
    const float* b_c    = (const float*)d_in[21];
    const float* W_v1   = (const float*)d_in[22];
    const float* b_v1   = (const float*)d_in[23];
    float* out = (float*)d_out;

    float *hpz, *hpu, *gpart, *sz, *su, *zcb, *cz, *cu, *xb, *gib, *ghb, *grub, *genb, *rmx, *rsm, *cpb;
    cudaGetSymbolAddress((void**)&hpz,  d_hproj_z);
    cudaGetSymbolAddress((void**)&hpu,  d_hproj_u);
    cudaGetSymbolAddress((void**)&gpart,d_gpart);
    cudaGetSymbolAddress((void**)&sz,   d_scores_z);
    cudaGetSymbolAddress((void**)&su,   d_scores_u);
    cudaGetSymbolAddress((void**)&zcb,  d_zc);
    cudaGetSymbolAddress((void**)&cz,   d_ctx_z);
    cudaGetSymbolAddress((void**)&cu,   d_ctx_u);
    cudaGetSymbolAddress((void**)&xb,   d_x);
    cudaGetSymbolAddress((void**)&gib,  d_gi);
    cudaGetSymbolAddress((void**)&ghb,  d_gh);
    cudaGetSymbolAddress((void**)&grub, d_gru);
    cudaGetSymbolAddress((void**)&genb, d_gen);
    cudaGetSymbolAddress((void**)&rmx,  d_rmax);
    cudaGetSymbolAddress((void**)&rsm,  d_rsum);
    cudaGetSymbolAddress((void**)&cpb,  d_cp);

    // zero atomic accumulators
    cudaMemsetAsync(hpz,  0, B * H  * sizeof(float));
    cudaMemsetAsync(hpu,  0, B * H  * sizeof(float));
    cudaMemsetAsync(gpart,0, B * H  * sizeof(float));
    cudaMemsetAsync(sz,   0, B * TZ * sizeof(float));
    cudaMemsetAsync(su,   0, B * TU * sizeof(float));
    cudaMemsetAsync(zcb,  0, B * TZ * sizeof(float));
    cudaMemsetAsync(genb, 0, B * V  * sizeof(float));

    // hidden-part of attention energies:  h @ Wa[:H] + ba
    skinny_proj<<<dim3(4, 4), 256>>>(h, H, Wa_z, H, ba_z, hpz, H, 256);
    skinny_proj<<<dim3(4, 4), 256>>>(h, H, Wa_u, H, ba_u, hpu, H, 256);

    // enc-part + tanh + dot(v) -> scores
    energy_score<<<dim3(16, (TZ * B) / BM), 256>>>(z_enc, Wa_z + H * H, hpz, v_z, sz, TZ * B, TZ);
    energy_score<<<dim3(16, (TU * B) / BM), 256>>>(u_enc, Wa_u + H * H, hpu, v_u, su, TU * B, TU);

    // softmax + context
    attn_ctx<<<dim3(B, 4), 256>>>(sz, z_enc, cz, TZ);
    attn_ctx<<<dim3(B, 4), 256>>>(su, u_enc, cu, TU);

    // x = [ctx_z | ctx_u | emb gather]
    build_x<<<(B * XD + 255) / 256, 256>>>(cz, cu, emb, mt, xb);

    // GRU gates
    rowdot<<<G3 / 16, 256>>>(xb, XD, W_ih, b_ih, gib, G3);
    rowdot<<<G3 / 16, 256>>>(h,  H,  W_hh, b_hh, ghb, G3);

    // gates + layernorm; writes h_new into the tail of d_out
    gru_ln<<<B, 1024>>>(gib, ghb, h, ln_a, ln_b, out + (long)B * V, grub);

    // copy branch: gru-part of W_c, then fused z_enc@W_c[:H] + tanh + dot(W_v1)
    skinny_proj<<<dim3(4, 4), 256>>>(grub, H, W_c + H * H, H, b_c, gpart, H, 256);
    energy_score<<<dim3(16, (TZ * B) / BM), 256>>>(z_enc, W_c, gpart, W_v1, zcb, TZ * B, TZ);

    // vocab projection
    gen_gemm<<<dim3(V / 256, 4), 256>>>(grub, W_proj, genb);

    // joint softmax over [gen | zc], then combine with copy distribution
    softmax_stats<<<B, 256>>>(genb, b_proj, zcb, b_v1, rmx, rsm, cpb);
    final_combine<<<dim3(V / 256, B), 256>>>(genb, b_proj, pz, rmx, rsm, cpb, out);

    (void)in_sizes; (void)n_in; (void)out_size;
}